// round 7
// baseline (speedup 1.0000x reference)
#include <cuda_runtime.h>
#include <cuda_bf16.h>
#include <cstdint>

#define BATCH 64
#define CH 64
#define HH 112
#define WW 112
#define HWPIX (HH*WW)          // 12544
#define NP 64                  // pixels per tile
#define TPB 14
#define BLKX 14                // 14*14*64 = 12544
#define EPSV 1e-5f

// device scratch (no cudaMalloc allowed)
__device__ float g_context[BATCH*CH*CH];   // [b][c][d]
__device__ float g_dynw[BATCH*CH*9];       // [b*c][9]

// ---------------- smem layout (bytes) ----------------
// X  : [64 ch][72 stride] bf16 (hi,lo), DOUBLE buffered   4 x 9216
// W  : [128 out][72 stride] bf16 (hi,lo)                  2 x 18432
// KV : [64 px][136 stride] bf16 (hi,lo); cols 0-63 V, 64-127 K   2 x 17408
#define XSTR  72
#define WSTR  72
#define KVSTR 136
#define XHB   9216             // hi->lo delta within an X buffer
#define OFF_XHI0 0
#define OFF_XHI1 18432
#define OFF_WHI  36864
#define OFF_WLO  55296
#define OFF_KHI  73728
#define OFF_KLO  91136
#define SMEMB    108544

// ---------------- helpers ----------------
__device__ __forceinline__ uint32_t smem_u32(const void* p){
  uint32_t a;
  asm("{ .reg .u64 t; cvta.to.shared.u64 t, %1; cvt.u32.u64 %0, t; }" : "=r"(a) : "l"(p));
  return a;
}
__device__ __forceinline__ void ldsm4(uint32_t* r, uint32_t addr){
  asm volatile("ldmatrix.sync.aligned.m8n8.x4.shared.b16 {%0,%1,%2,%3}, [%4];"
    : "=r"(r[0]), "=r"(r[1]), "=r"(r[2]), "=r"(r[3]) : "r"(addr));
}
__device__ __forceinline__ void ldsm4t(uint32_t* r, uint32_t addr){
  asm volatile("ldmatrix.sync.aligned.m8n8.x4.trans.shared.b16 {%0,%1,%2,%3}, [%4];"
    : "=r"(r[0]), "=r"(r[1]), "=r"(r[2]), "=r"(r[3]) : "r"(addr));
}
__device__ __forceinline__ void mma16816(float* d, const uint32_t* a, uint32_t b0, uint32_t b1){
  asm volatile("mma.sync.aligned.m16n8k16.row.col.f32.bf16.bf16.f32 "
    "{%0,%1,%2,%3}, {%4,%5,%6,%7}, {%8,%9}, {%0,%1,%2,%3};"
    : "+f"(d[0]), "+f"(d[1]), "+f"(d[2]), "+f"(d[3])
    : "r"(a[0]), "r"(a[1]), "r"(a[2]), "r"(a[3]), "r"(b0), "r"(b1));
}
// truncation split: hi = bits & 0xffff0000 (exact bf16), lo = rn_bf16(f - hi)
__device__ __forceinline__ void split_store(uint32_t* ph, uint32_t* pl, int bi,
                                            float f0, float f1){
  uint32_t u0 = __float_as_uint(f0), u1 = __float_as_uint(f1);
  ph[bi] = __byte_perm(u0, u1, 0x7632);                 // [hi16(u0), hi16(u1)]
  float h0 = __uint_as_float(u0 & 0xffff0000u);
  float h1 = __uint_as_float(u1 & 0xffff0000u);
  __nv_bfloat162 t = __floats2bfloat162_rn(f0 - h0, f1 - h1);
  pl[bi] = *(uint32_t*)&t;
}

__global__ void __launch_bounds__(256) zero_ctx_kernel(){
  int i = blockIdx.x * blockDim.x + threadIdx.x;   // 65536 float4
  ((float4*)g_context)[i] = make_float4(0.f,0.f,0.f,0.f);
}

// ============ fused attention: bf16x3 split HMMA, 2 CTAs/SM ============
__global__ void __launch_bounds__(256, 2) attn_ctx_mma(
    const float* __restrict__ x,
    const float* __restrict__ Wv, const float* __restrict__ bvp,
    const float* __restrict__ Wm, const float* __restrict__ bm,
    const float* __restrict__ gma, const float* __restrict__ bta,
    const float* __restrict__ mu,  const float* __restrict__ var)
{
  extern __shared__ char smc[];
  const uint32_t sb = smem_u32(smc);
  const int tid = threadIdx.x;
  const int w   = tid >> 5;        // warp 0..7
  const int l   = tid & 31;
  const int b   = blockIdx.y;

  const int lk = (l & 7) + 8 * (l >> 4);     // ldmatrix row term
  const int lc = 8 * ((l >> 3) & 1);         // ldmatrix col term
  const int cl2 = 2 * (l & 3);

  const int px_base  = (w & 3) * 16;         // stage-1 pixel rows of this warp
  const int out_base = (w >> 2) * 64;        // 0 = V warps, 64 = K warps
  const bool isK = (out_base != 0);

  const float* xb = x + (size_t)b * CH * HWPIX;

  // ---- prefetch X tile 0 into registers ----
  float4 xr[4];
  {
    const int n0 = blockIdx.x * TPB * NP;
    #pragma unroll
    for (int i = 0; i < 4; i++) {
      int f4 = tid + 256 * i;          // 1024 float4 = 64ch x 16 f4
      int chn = f4 >> 4, pxf = f4 & 15;
      xr[i] = __ldg((const float4*)(xb + (size_t)chn * HWPIX + n0) + pxf);
    }
  }

  // ---- load W (rows 0-63 = Wv, 64-127 = Wm*bnscale), bf16 hi/lo, once ----
  {
    uint32_t* ph = (uint32_t*)(smc + OFF_WHI);
    uint32_t* pl = (uint32_t*)(smc + OFF_WLO);
    #pragma unroll
    for (int i = 0; i < 8; i++) {
      int f4 = tid + 256 * i;        // 2048 float4
      int o  = f4 >> 4;
      int c4 = (f4 & 15) * 4;
      float4 v;
      float s = 1.f;
      if (o < 64) v = __ldg((const float4*)(Wv + o*64 + c4));
      else {
        int oo = o - 64;
        v = __ldg((const float4*)(Wm + oo*64 + c4));
        s = __ldg(gma + oo) * rsqrtf(__ldg(var + oo) + EPSV);
      }
      v.x *= s; v.y *= s; v.z *= s; v.w *= s;
      int bi = o * (WSTR/2) + (c4 >> 1);
      split_store(ph, pl, bi,     v.x, v.y);
      split_store(ph, pl, bi + 1, v.z, v.w);
    }
  }

  // ---- per-thread constants: K warps -> BN shift, V warps -> bias ----
  float cst[16];
  #pragma unroll
  for (int nt = 0; nt < 8; nt++)
    #pragma unroll
    for (int j = 0; j < 2; j++) {
      int ch = nt*8 + cl2 + j;
      if (isK) {
        float sc = __ldg(gma + ch) * rsqrtf(__ldg(var + ch) + EPSV);
        cst[2*nt + j] = (__ldg(bm + ch) - __ldg(mu + ch)) * sc + __ldg(bta + ch);
      } else {
        cst[2*nt + j] = __ldg(bvp + ch);
      }
    }

  // ---- stage-2 persistent accumulators ----
  const int c_base = (w >> 1) * 16;
  const int d_base = (w & 1) * 32;
  float acc2[4][4];
  #pragma unroll
  for (int i = 0; i < 4; i++)
    #pragma unroll
    for (int j = 0; j < 4; j++) acc2[i][j] = 0.f;

  // ldmatrix base byte offsets
  const uint32_t a1term = (uint32_t)(lk*XSTR + px_base + lc) * 2;
  const uint32_t b1off  = sb + OFF_WHI + (uint32_t)((out_base + lk)*WSTR + lc) * 2;
  const uint32_t a2off  = sb + OFF_KHI + (uint32_t)(lk*KVSTR + 64 + c_base + lc) * 2;
  const uint32_t b2off  = sb + OFF_KHI + (uint32_t)(lk*KVSTR + d_base + lc) * 2;

  for (int t = 0; t < TPB; t++) {
    const uint32_t xhi = (t & 1) ? OFF_XHI1 : OFF_XHI0;

    // ---- convert + store X(t) from regs into buffer t&1 ----
    {
      uint32_t* ph = (uint32_t*)(smc + xhi);
      uint32_t* pl = (uint32_t*)(smc + xhi + XHB);
      #pragma unroll
      for (int i = 0; i < 4; i++) {
        int f4  = tid + 256 * i;
        int chn = f4 >> 4, pxf = f4 & 15;
        int bi = chn * (XSTR/2) + pxf * 2;
        split_store(ph, pl, bi,     xr[i].x, xr[i].y);
        split_store(ph, pl, bi + 1, xr[i].z, xr[i].w);
      }
    }
    __syncthreads();

    // ---- prefetch X(t+1) ----
    if (t + 1 < TPB) {
      const int n1 = (blockIdx.x * TPB + t + 1) * NP;
      #pragma unroll
      for (int i = 0; i < 4; i++) {
        int f4 = tid + 256 * i;
        int chn = f4 >> 4, pxf = f4 & 15;
        xr[i] = __ldg((const float4*)(xb + (size_t)chn * HWPIX + n1) + pxf);
      }
    }

    // ---- stage 1: D1[16 px of warp][64 out of warp] = X @ W^T, bf16x3 ----
    float acc1[8][4];
    #pragma unroll
    for (int i = 0; i < 8; i++)
      #pragma unroll
      for (int j = 0; j < 4; j++) acc1[i][j] = 0.f;

    const uint32_t a1off = sb + xhi + a1term;
    #pragma unroll
    for (int ks = 0; ks < 4; ks++) {
      uint32_t ah[4], al[4];
      uint32_t astep = (uint32_t)(ks * 16 * XSTR) * 2;
      ldsm4t(ah, a1off + astep);
      ldsm4t(al, a1off + astep + XHB);
      #pragma unroll
      for (int nb = 0; nb < 4; nb++) {
        uint32_t bh[4], bl[4];
        uint32_t bo = (uint32_t)((nb*16) * WSTR + ks*16) * 2;
        ldsm4(bh, b1off + bo);
        ldsm4(bl, b1off + bo + 18432u);
        mma16816(acc1[2*nb],   ah, bh[0], bh[1]);
        mma16816(acc1[2*nb],   ah, bl[0], bl[1]);
        mma16816(acc1[2*nb],   al, bh[0], bh[1]);
        mma16816(acc1[2*nb+1], ah, bh[2], bh[3]);
        mma16816(acc1[2*nb+1], ah, bl[2], bl[3]);
        mma16816(acc1[2*nb+1], al, bh[2], bh[3]);
      }
    }

    // ---- K warps: softmax over all 64 channels (warp-local) ----
    float inv0 = 0.f, inv1 = 0.f;
    if (isK) {
      float m0 = -1e30f, m1 = -1e30f;
      #pragma unroll
      for (int nt = 0; nt < 8; nt++)
        #pragma unroll
        for (int j = 0; j < 2; j++) {
          float sh = cst[2*nt + j];
          acc1[nt][j]   += sh;
          acc1[nt][2+j] += sh;
          m0 = fmaxf(m0, acc1[nt][j]);
          m1 = fmaxf(m1, acc1[nt][2+j]);
        }
      m0 = fmaxf(m0, __shfl_xor_sync(0xffffffffu, m0, 1));
      m0 = fmaxf(m0, __shfl_xor_sync(0xffffffffu, m0, 2));
      m1 = fmaxf(m1, __shfl_xor_sync(0xffffffffu, m1, 1));
      m1 = fmaxf(m1, __shfl_xor_sync(0xffffffffu, m1, 2));
      float s0 = 0.f, s1 = 0.f;
      #pragma unroll
      for (int nt = 0; nt < 8; nt++)
        #pragma unroll
        for (int j = 0; j < 2; j++) {
          acc1[nt][j]   = __expf(acc1[nt][j]   - m0); s0 += acc1[nt][j];
          acc1[nt][2+j] = __expf(acc1[nt][2+j] - m1); s1 += acc1[nt][2+j];
        }
      s0 += __shfl_xor_sync(0xffffffffu, s0, 1);
      s0 += __shfl_xor_sync(0xffffffffu, s0, 2);
      s1 += __shfl_xor_sync(0xffffffffu, s1, 1);
      s1 += __shfl_xor_sync(0xffffffffu, s1, 2);
      inv0 = 1.f / s0; inv1 = 1.f / s1;
    }

    // ---- write KV smem [px][out] bf16 hi/lo ----
    {
      const int r0 = px_base + (l >> 2);
      uint32_t* ph = (uint32_t*)(smc + OFF_KHI);
      uint32_t* pl = (uint32_t*)(smc + OFF_KLO);
      #pragma unroll
      for (int nt = 0; nt < 8; nt++) {
        float f0, f1, f2, f3;
        if (isK) {
          f0 = acc1[nt][0] * inv0;          f1 = acc1[nt][1] * inv0;
          f2 = acc1[nt][2] * inv1;          f3 = acc1[nt][3] * inv1;
        } else {
          f0 = acc1[nt][0] + cst[2*nt];     f1 = acc1[nt][1] + cst[2*nt+1];
          f2 = acc1[nt][2] + cst[2*nt];     f3 = acc1[nt][3] + cst[2*nt+1];
        }
        int col = out_base + nt*8 + cl2;
        int bi0 = r0      * (KVSTR/2) + (col >> 1);
        int bi1 = (r0 + 8)* (KVSTR/2) + (col >> 1);
        split_store(ph, pl, bi0, f0, f1);
        split_store(ph, pl, bi1, f2, f3);
      }
    }
    __syncthreads();

    // ---- stage 2: ctx[c,d] += K[c,px] @ V[d,px]^T over 64 px, bf16x3 ----
    #pragma unroll
    for (int ks = 0; ks < 4; ks++) {
      uint32_t step = (uint32_t)(ks * 16 * KVSTR) * 2;
      uint32_t ah[4], al[4];
      ldsm4t(ah, a2off + step);
      ldsm4t(al, a2off + step + 17408u);
      #pragma unroll
      for (int dbi = 0; dbi < 2; dbi++) {
        uint32_t bh[4], bl[4];
        uint32_t bo = step + (uint32_t)(dbi * 16) * 2;
        ldsm4t(bh, b2off + bo);
        ldsm4t(bl, b2off + bo + 17408u);
        mma16816(acc2[2*dbi],   ah, bh[0], bh[2]);
        mma16816(acc2[2*dbi],   ah, bl[0], bl[2]);
        mma16816(acc2[2*dbi],   al, bh[0], bh[2]);
        mma16816(acc2[2*dbi+1], ah, bh[1], bh[3]);
        mma16816(acc2[2*dbi+1], ah, bl[1], bl[3]);
        mma16816(acc2[2*dbi+1], al, bh[1], bh[3]);
      }
    }
    // no trailing barrier: X double-buffered; KV(t) rewritten only after sync1(t+1).
  }

  // ---- flush context ----
  float* cp = g_context + (size_t)b * CH * CH;
  const int c0 = c_base + (l >> 2);
  #pragma unroll
  for (int nt = 0; nt < 4; nt++)
    #pragma unroll
    for (int j = 0; j < 2; j++) {
      int d = d_base + nt*8 + cl2 + j;
      atomicAdd(cp + c0*CH + d,       acc2[nt][j]);
      atomicAdd(cp + (c0+8)*CH + d,   acc2[nt][2+j]);
    }
}

// dynw[b,i,j] = sum_m sigmoid(context[b,i,m]) * Wfc[i,j,m] + bfc[i,j]
__global__ void __launch_bounds__(128) dynw_kernel(
    const float* __restrict__ Wfc, const float* __restrict__ bfc)
{
  int warp = blockIdx.x * 4 + (threadIdx.x >> 5);   // 0..4095
  int lane = threadIdx.x & 31;
  int i = warp & 63;
  const float* ctx = g_context + (size_t)warp * 64;
  float a0 = 1.f / (1.f + __expf(-ctx[lane]));
  float a1 = 1.f / (1.f + __expf(-ctx[lane + 32]));
  #pragma unroll
  for (int j = 0; j < 9; j++) {
    float s = a0 * Wfc[(i*9 + j)*64 + lane] + a1 * Wfc[(i*9 + j)*64 + lane + 32];
    #pragma unroll
    for (int o = 16; o > 0; o >>= 1) s += __shfl_xor_sync(0xffffffffu, s, o);
    if (lane == 0) g_dynw[warp*9 + j] = s + bfc[i*9 + j];
  }
}

// depthwise 3x3, pad 1 — float4 per thread, 8 row-groups of 7 rows
#define TROWS 56
#define TS_STR 120
__global__ void __launch_bounds__(256) dwconv_kernel(
    const float* __restrict__ x, float* __restrict__ out)
{
  __shared__ float ts[(TROWS + 2) * TS_STR];   // data col s at idx s+4
  const int plane = blockIdx.x;                 // b*64 + c
  const int rb = blockIdx.y * TROWS;
  const float* xp = x + (size_t)plane * HWPIX;
  const int tid = threadIdx.x;

  // float4 fill: 58 rows x 28 float4
  for (int i = tid; i < 1624; i += 256) {
    int r = i / 28, k = i - r * 28;
    int gr = rb - 1 + r;
    float4 v = make_float4(0.f, 0.f, 0.f, 0.f);
    if (gr >= 0 && gr < HH) v = __ldg((const float4*)(xp + (size_t)gr * WW) + k);
    *(float4*)&ts[r * TS_STR + 4 + 4*k] = v;
  }
  for (int i = tid; i < 58; i += 256) { ts[i*TS_STR + 3] = 0.f; ts[i*TS_STR + 116] = 0.f; }

  float w[9];
  const float* wp = g_dynw + (size_t)plane * 9;
  #pragma unroll
  for (int k = 0; k < 9; k++) w[k] = __ldg(wp + k);
  __syncthreads();

  if (tid < 224) {
    const int g  = tid >> 5 ;        // nope — need /28; compute directly
  }
  if (tid < 224) {
    const int g  = tid / 28;         // row group 0..7 (7 rows each)
    const int c4 = tid - g * 28;     // float4 column 0..27
    const float* rp = ts + (g*7) * TS_STR + 4*c4 + 3;
    float  L0 = rp[0];  float4 F0 = *(const float4*)(rp + 1);  float R0 = rp[5];
    rp += TS_STR;
    float  L1 = rp[0];  float4 F1 = *(const float4*)(rp + 1);  float R1 = rp[5];
    float* op = out + (size_t)plane * HWPIX + (size_t)(rb + g*7) * WW + 4*c4;
    #pragma unroll
    for (int j = 0; j < 7; j++) {
      rp += TS_STR;
      float  L2 = rp[0];  float4 F2 = *(const float4*)(rp + 1);  float R2 = rp[5];
      float4 o;
      o.x = w[0]*L0   + w[1]*F0.x + w[2]*F0.y
          + w[3]*L1   + w[4]*F1.x + w[5]*F1.y
          + w[6]*L2   + w[7]*F2.x + w[8]*F2.y;
      o.y = w[0]*F0.x + w[1]*F0.y + w[2]*F0.z
          + w[3]*F1.x + w[4]*F1.y + w[5]*F1.z
          + w[6]*F2.x + w[7]*F2.y + w[8]*F2.z;
      o.z = w[0]*F0.y + w[1]*F0.z + w[2]*F0.w
          + w[3]*F1.y + w[4]*F1.z + w[5]*F1.w
          + w[6]*F2.y + w[7]*F2.z + w[8]*F2.w;
      o.w = w[0]*F0.z + w[1]*F0.w + w[2]*R0
          + w[3]*F1.z + w[4]*F1.w + w[5]*R1
          + w[6]*F2.z + w[7]*F2.w + w[8]*R2;
      *(float4*)op = o;
      op += WW;
      L0 = L1; F0 = F1; R0 = R1;
      L1 = L2; F1 = F2; R1 = R2;
    }
  }
}

extern "C" void kernel_launch(void* const* d_in, const int* in_sizes, int n_in,
                              void* d_out, int out_size)
{
  const float* x    = (const float*)d_in[0];
  const float* Wv   = (const float*)d_in[1];
  const float* bv   = (const float*)d_in[2];
  const float* Wm   = (const float*)d_in[3];
  const float* bm   = (const float*)d_in[4];
  const float* gma  = (const float*)d_in[5];
  const float* bta  = (const float*)d_in[6];
  const float* mu   = (const float*)d_in[7];
  const float* var  = (const float*)d_in[8];
  const float* Wfc  = (const float*)d_in[9];
  const float* bfc  = (const float*)d_in[10];
  float* out = (float*)d_out;

  cudaFuncSetAttribute(attn_ctx_mma,
                       cudaFuncAttributeMaxDynamicSharedMemorySize, SMEMB);

  zero_ctx_kernel<<<256, 256>>>();
  attn_ctx_mma<<<dim3(BLKX, BATCH), 256, SMEMB>>>(
      x, Wv, bv, Wm, bm, gma, bta, mu, var);
  dynw_kernel<<<1024, 128>>>(Wfc, bfc);
  dwconv_kernel<<<dim3(BATCH * CH, HH / TROWS), 256>>>(x, out);
}

// round 8
// speedup vs baseline: 1.3755x; 1.3755x over previous
#include <cuda_runtime.h>
#include <cuda_bf16.h>
#include <cstdint>

#define BATCH 64
#define CH 64
#define HH 112
#define WW 112
#define HWPIX (HH*WW)          // 12544
#define NP 128                 // pixels per tile
#define TPB 7
#define BLKX 14                // 14*7*128 = 12544
#define EPSV 1e-5f

// device scratch (no cudaMalloc allowed)
__device__ float g_context[BATCH*CH*CH];   // [b][c][d]
__device__ float g_dynw[BATCH*CH*9];       // [b*c][9]

// ---------------- smem layout (bytes) ----------------
// X  : [64 ch][136 stride] bf16 (hi,lo), DOUBLE buffered
// W  : [128 out][72 stride] bf16 (hi,lo)
// KV : [128 px][136 stride] bf16 (hi,lo); cols 0-63 = V, 64-127 = K
#define XSTR  136
#define WSTR  72
#define KVSTR 136
#define OFF_XHI0 0
#define OFF_XLO0 17408
#define OFF_XHI1 34816
#define OFF_XLO1 52224
#define OFF_WHI  69632
#define OFF_WLO  88064
#define OFF_KHI  106496
#define OFF_KLO  141312
#define SMEMB    176128

// ---------------- helpers ----------------
__device__ __forceinline__ uint32_t smem_u32(const void* p){
  uint32_t a;
  asm("{ .reg .u64 t; cvta.to.shared.u64 t, %1; cvt.u32.u64 %0, t; }" : "=r"(a) : "l"(p));
  return a;
}
__device__ __forceinline__ void ldsm4(uint32_t* r, uint32_t addr){
  asm volatile("ldmatrix.sync.aligned.m8n8.x4.shared.b16 {%0,%1,%2,%3}, [%4];"
    : "=r"(r[0]), "=r"(r[1]), "=r"(r[2]), "=r"(r[3]) : "r"(addr));
}
__device__ __forceinline__ void ldsm4t(uint32_t* r, uint32_t addr){
  asm volatile("ldmatrix.sync.aligned.m8n8.x4.trans.shared.b16 {%0,%1,%2,%3}, [%4];"
    : "=r"(r[0]), "=r"(r[1]), "=r"(r[2]), "=r"(r[3]) : "r"(addr));
}
__device__ __forceinline__ void mma16816(float* d, const uint32_t* a, uint32_t b0, uint32_t b1){
  asm volatile("mma.sync.aligned.m16n8k16.row.col.f32.bf16.bf16.f32 "
    "{%0,%1,%2,%3}, {%4,%5,%6,%7}, {%8,%9}, {%0,%1,%2,%3};"
    : "+f"(d[0]), "+f"(d[1]), "+f"(d[2]), "+f"(d[3])
    : "r"(a[0]), "r"(a[1]), "r"(a[2]), "r"(a[3]), "r"(b0), "r"(b1));
}
// truncation split: hi = bits & 0xffff0000 (exact bf16), lo = rn_bf16(f - hi)
__device__ __forceinline__ void split_store(uint32_t* ph, uint32_t* pl, int bi,
                                            float f0, float f1){
  uint32_t u0 = __float_as_uint(f0), u1 = __float_as_uint(f1);
  ph[bi] = __byte_perm(u0, u1, 0x7632);                 // [hi16(u0), hi16(u1)]
  float h0 = __uint_as_float(u0 & 0xffff0000u);
  float h1 = __uint_as_float(u1 & 0xffff0000u);
  __nv_bfloat162 t = __floats2bfloat162_rn(f0 - h0, f1 - h1);
  pl[bi] = *(uint32_t*)&t;
}

__global__ void __launch_bounds__(256) zero_ctx_kernel(){
  int i = blockIdx.x * blockDim.x + threadIdx.x;   // 65536 float4
  ((float4*)g_context)[i] = make_float4(0.f,0.f,0.f,0.f);
}

// ============ fused attention: bf16x3 split HMMA, 16 warps ============
__global__ void __launch_bounds__(512, 1) attn_ctx_mma(
    const float* __restrict__ x,
    const float* __restrict__ Wv, const float* __restrict__ bvp,
    const float* __restrict__ Wm, const float* __restrict__ bm,
    const float* __restrict__ gma, const float* __restrict__ bta,
    const float* __restrict__ mu,  const float* __restrict__ var)
{
  extern __shared__ char smc[];
  const uint32_t sb = smem_u32(smc);
  const int tid = threadIdx.x;
  const int w   = tid >> 5;        // warp 0..15
  const int l   = tid & 31;
  const int b   = blockIdx.y;

  const int lk = (l & 7) + 8 * (l >> 4);     // ldmatrix row term
  const int lc = 8 * ((l >> 3) & 1);         // ldmatrix col term
  const int cl2 = 2 * (l & 3);

  // stage-1 roles: warp w -> px rows (w&7)*16, out cols (w>>3)*64
  const int pxb = (w & 7) * 16;
  const int ob  = (w >> 3) * 64;             // 0 = V warps, 64 = K warps
  const bool isK = (ob != 0);

  const float* xb = x + (size_t)b * CH * HWPIX;

  // ---- prefetch X tile 0 into registers ----
  float4 xr[4];
  {
    const int n0 = blockIdx.x * TPB * NP;
    #pragma unroll
    for (int i = 0; i < 4; i++) {
      int f4 = tid + 512 * i;          // 2048 float4 = 64ch x 32 f4
      int chn = f4 >> 5, pxf = f4 & 31;
      xr[i] = __ldg((const float4*)(xb + (size_t)chn * HWPIX + n0) + pxf);
    }
  }

  // ---- load W (rows 0-63 = Wv, 64-127 = Wm*bnscale), bf16 hi/lo, once ----
  {
    uint32_t* ph = (uint32_t*)(smc + OFF_WHI);
    uint32_t* pl = (uint32_t*)(smc + OFF_WLO);
    #pragma unroll
    for (int i = 0; i < 4; i++) {
      int f4 = tid + 512 * i;        // 2048 float4
      int o  = f4 >> 4;
      int c4 = (f4 & 15) * 4;
      float4 v;
      float s = 1.f;
      if (o < 64) v = __ldg((const float4*)(Wv + o*64 + c4));
      else {
        int oo = o - 64;
        v = __ldg((const float4*)(Wm + oo*64 + c4));
        s = __ldg(gma + oo) * rsqrtf(__ldg(var + oo) + EPSV);
      }
      v.x *= s; v.y *= s; v.z *= s; v.w *= s;
      int bi = o * (WSTR/2) + (c4 >> 1);
      split_store(ph, pl, bi,     v.x, v.y);
      split_store(ph, pl, bi + 1, v.z, v.w);
    }
  }

  // ---- per-thread constants: K warps -> BN shift, V warps -> bias ----
  float cst[16];
  #pragma unroll
  for (int nt = 0; nt < 8; nt++)
    #pragma unroll
    for (int j = 0; j < 2; j++) {
      int ch = nt*8 + cl2 + j;
      if (isK) {
        float sc = __ldg(gma + ch) * rsqrtf(__ldg(var + ch) + EPSV);
        cst[2*nt + j] = (__ldg(bm + ch) - __ldg(mu + ch)) * sc + __ldg(bta + ch);
      } else {
        cst[2*nt + j] = __ldg(bvp + ch);
      }
    }

  // ---- stage-2 persistent accumulators: warp w -> c[(w>>2)*16), d[(w&3)*16) ----
  const int c_base = (w >> 2) * 16;
  const int d_base = (w & 3) * 16;
  float acc2[2][4];
  #pragma unroll
  for (int i = 0; i < 2; i++)
    #pragma unroll
    for (int j = 0; j < 4; j++) acc2[i][j] = 0.f;

  // ldmatrix base byte offsets
  const uint32_t a1term = (uint32_t)(lk*XSTR + pxb + lc) * 2;
  const uint32_t b1off  = sb + OFF_WHI + (uint32_t)((ob + lk)*WSTR + lc) * 2;
  const uint32_t a2off  = sb + OFF_KHI + (uint32_t)(lk*KVSTR + 64 + c_base + lc) * 2;
  const uint32_t b2off  = sb + OFF_KHI + (uint32_t)(lk*KVSTR + d_base + lc) * 2;

  for (int t = 0; t < TPB; t++) {
    const uint32_t xhi = (t & 1) ? OFF_XHI1 : OFF_XHI0;

    // ---- convert + store X(t) from regs into buffer t&1 ----
    {
      uint32_t* ph = (uint32_t*)(smc + xhi);
      uint32_t* pl = (uint32_t*)(smc + xhi + 17408);
      #pragma unroll
      for (int i = 0; i < 4; i++) {
        int f4  = tid + 512 * i;
        int chn = f4 >> 5, pxf = f4 & 31;
        int bi = chn * (XSTR/2) + pxf * 2;
        split_store(ph, pl, bi,     xr[i].x, xr[i].y);
        split_store(ph, pl, bi + 1, xr[i].z, xr[i].w);
      }
    }
    __syncthreads();

    // ---- prefetch X(t+1) (latency hidden behind stage1 MMAs) ----
    if (t + 1 < TPB) {
      const int n1 = (blockIdx.x * TPB + t + 1) * NP;
      #pragma unroll
      for (int i = 0; i < 4; i++) {
        int f4 = tid + 512 * i;
        int chn = f4 >> 5, pxf = f4 & 31;
        xr[i] = __ldg((const float4*)(xb + (size_t)chn * HWPIX + n1) + pxf);
      }
    }

    // ---- stage 1: D1[16 px of warp][64 out of warp] = X @ W^T, bf16x3 ----
    float acc1[8][4];
    #pragma unroll
    for (int i = 0; i < 8; i++)
      #pragma unroll
      for (int j = 0; j < 4; j++) acc1[i][j] = 0.f;

    const uint32_t a1off = sb + xhi + a1term;
    #pragma unroll
    for (int ks = 0; ks < 4; ks++) {
      uint32_t ah[4], al[4];
      uint32_t astep = (uint32_t)(ks * 16 * XSTR) * 2;
      ldsm4t(ah, a1off + astep);
      ldsm4t(al, a1off + astep + 17408u);
      #pragma unroll
      for (int nb = 0; nb < 4; nb++) {
        uint32_t bh[4], bl[4];
        uint32_t bo = (uint32_t)((nb*16) * WSTR + ks*16) * 2;
        ldsm4(bh, b1off + bo);
        ldsm4(bl, b1off + bo + 18432u);
        mma16816(acc1[2*nb],   ah, bh[0], bh[1]);
        mma16816(acc1[2*nb],   ah, bl[0], bl[1]);
        mma16816(acc1[2*nb],   al, bh[0], bh[1]);
        mma16816(acc1[2*nb+1], ah, bh[2], bh[3]);
        mma16816(acc1[2*nb+1], ah, bl[2], bl[3]);
        mma16816(acc1[2*nb+1], al, bh[2], bh[3]);
      }
    }

    // ---- K warps: softmax over all 64 channels (warp-local) ----
    float inv0 = 0.f, inv1 = 0.f;
    if (isK) {
      float m0 = -1e30f, m1 = -1e30f;
      #pragma unroll
      for (int nt = 0; nt < 8; nt++)
        #pragma unroll
        for (int j = 0; j < 2; j++) {
          float sh = cst[2*nt + j];
          acc1[nt][j]   += sh;
          acc1[nt][2+j] += sh;
          m0 = fmaxf(m0, acc1[nt][j]);
          m1 = fmaxf(m1, acc1[nt][2+j]);
        }
      m0 = fmaxf(m0, __shfl_xor_sync(0xffffffffu, m0, 1));
      m0 = fmaxf(m0, __shfl_xor_sync(0xffffffffu, m0, 2));
      m1 = fmaxf(m1, __shfl_xor_sync(0xffffffffu, m1, 1));
      m1 = fmaxf(m1, __shfl_xor_sync(0xffffffffu, m1, 2));
      float s0 = 0.f, s1 = 0.f;
      #pragma unroll
      for (int nt = 0; nt < 8; nt++)
        #pragma unroll
        for (int j = 0; j < 2; j++) {
          acc1[nt][j]   = __expf(acc1[nt][j]   - m0); s0 += acc1[nt][j];
          acc1[nt][2+j] = __expf(acc1[nt][2+j] - m1); s1 += acc1[nt][2+j];
        }
      s0 += __shfl_xor_sync(0xffffffffu, s0, 1);
      s0 += __shfl_xor_sync(0xffffffffu, s0, 2);
      s1 += __shfl_xor_sync(0xffffffffu, s1, 1);
      s1 += __shfl_xor_sync(0xffffffffu, s1, 2);
      inv0 = 1.f / s0; inv1 = 1.f / s1;
    }

    // ---- write KV smem [px][out] bf16 hi/lo ----
    {
      const int r0 = pxb + (l >> 2);
      uint32_t* ph = (uint32_t*)(smc + OFF_KHI);
      uint32_t* pl = (uint32_t*)(smc + OFF_KLO);
      #pragma unroll
      for (int nt = 0; nt < 8; nt++) {
        float f0, f1, f2, f3;
        if (isK) {
          f0 = acc1[nt][0] * inv0;          f1 = acc1[nt][1] * inv0;
          f2 = acc1[nt][2] * inv1;          f3 = acc1[nt][3] * inv1;
        } else {
          f0 = acc1[nt][0] + cst[2*nt];     f1 = acc1[nt][1] + cst[2*nt+1];
          f2 = acc1[nt][2] + cst[2*nt];     f3 = acc1[nt][3] + cst[2*nt+1];
        }
        int col = ob + nt*8 + cl2;
        int bi0 = r0       * (KVSTR/2) + (col >> 1);
        int bi1 = (r0 + 8) * (KVSTR/2) + (col >> 1);
        split_store(ph, pl, bi0, f0, f1);
        split_store(ph, pl, bi1, f2, f3);
      }
    }
    __syncthreads();

    // ---- stage 2: ctx[c,d] += K[c,px] @ V[d,px]^T over 128 px, bf16x3 ----
    #pragma unroll
    for (int ks = 0; ks < 8; ks++) {
      uint32_t step = (uint32_t)(ks * 16 * KVSTR) * 2;
      uint32_t ah[4], al[4];
      ldsm4t(ah, a2off + step);
      ldsm4t(al, a2off + step + 34816u);
      uint32_t bh[4], bl[4];
      ldsm4t(bh, b2off + step);
      ldsm4t(bl, b2off + step + 34816u);
      // trans-x4 order: r0=b(nt0,k0), r1=b(nt1,k0), r2=b(nt0,k1), r3=b(nt1,k1)
      mma16816(acc2[0], ah, bh[0], bh[2]);
      mma16816(acc2[0], ah, bl[0], bl[2]);
      mma16816(acc2[0], al, bh[0], bh[2]);
      mma16816(acc2[1], ah, bh[1], bh[3]);
      mma16816(acc2[1], ah, bl[1], bl[3]);
      mma16816(acc2[1], al, bh[1], bh[3]);
    }
    // no trailing barrier: X double-buffered; KV(t) rewritten only after sync1(t+1).
  }

  // ---- flush context ----
  float* cp = g_context + (size_t)b * CH * CH;
  const int c0 = c_base + (l >> 2);
  #pragma unroll
  for (int nt = 0; nt < 2; nt++)
    #pragma unroll
    for (int j = 0; j < 2; j++) {
      int d = d_base + nt*8 + cl2 + j;
      atomicAdd(cp + c0*CH + d,       acc2[nt][j]);
      atomicAdd(cp + (c0+8)*CH + d,   acc2[nt][2+j]);
    }
}

// dynw[b,i,j] = sum_m sigmoid(context[b,i,m]) * Wfc[i,j,m] + bfc[i,j]
__global__ void __launch_bounds__(128) dynw_kernel(
    const float* __restrict__ Wfc, const float* __restrict__ bfc)
{
  int warp = blockIdx.x * 4 + (threadIdx.x >> 5);   // 0..4095
  int lane = threadIdx.x & 31;
  int i = warp & 63;
  const float* ctx = g_context + (size_t)warp * 64;
  float a0 = 1.f / (1.f + __expf(-ctx[lane]));
  float a1 = 1.f / (1.f + __expf(-ctx[lane + 32]));
  #pragma unroll
  for (int j = 0; j < 9; j++) {
    float s = a0 * Wfc[(i*9 + j)*64 + lane] + a1 * Wfc[(i*9 + j)*64 + lane + 32];
    #pragma unroll
    for (int o = 16; o > 0; o >>= 1) s += __shfl_xor_sync(0xffffffffu, s, o);
    if (lane == 0) g_dynw[warp*9 + j] = s + bfc[i*9 + j];
  }
}

// depthwise 3x3, pad 1 — float4 per thread, 4 row-groups of 7 rows (round-6 proven)
#define TROWS 28
#define TS_STR 120
__global__ void __launch_bounds__(128) dwconv_kernel(
    const float* __restrict__ x, float* __restrict__ out)
{
  __shared__ float ts[(TROWS + 2) * TS_STR];   // data col s at idx s+4
  const int plane = blockIdx.x;                 // b*64 + c
  const int rb = blockIdx.y * TROWS;
  const float* xp = x + (size_t)plane * HWPIX;
  const int tid = threadIdx.x;

  // float4 fill: 30 rows x 28 float4
  for (int i = tid; i < 840; i += 128) {
    int r = i / 28, k = i - r * 28;
    int gr = rb - 1 + r;
    float4 v = make_float4(0.f, 0.f, 0.f, 0.f);
    if (gr >= 0 && gr < HH) v = __ldg((const float4*)(xp + (size_t)gr * WW) + k);
    *(float4*)&ts[r * TS_STR + 4 + 4*k] = v;
  }
  for (int i = tid; i < 30; i += 128) { ts[i*TS_STR + 3] = 0.f; ts[i*TS_STR + 116] = 0.f; }

  float w[9];
  const float* wp = g_dynw + (size_t)plane * 9;
  #pragma unroll
  for (int k = 0; k < 9; k++) w[k] = __ldg(wp + k);
  __syncthreads();

  if (tid < 112) {
    const int g  = tid / 28;         // row group 0..3 (7 rows each)
    const int c4 = tid - g * 28;     // float4 column 0..27
    const float* rp = ts + (g*7) * TS_STR + 4*c4 + 3;
    float  L0 = rp[0];  float4 F0 = *(const float4*)(rp + 1);  float R0 = rp[5];
    rp += TS_STR;
    float  L1 = rp[0];  float4 F1 = *(const float4*)(rp + 1);  float R1 = rp[5];
    float* op = out + (size_t)plane * HWPIX + (size_t)(rb + g*7) * WW + 4*c4;
    #pragma unroll
    for (int j = 0; j < 7; j++) {
      rp += TS_STR;
      float  L2 = rp[0];  float4 F2 = *(const float4*)(rp + 1);  float R2 = rp[5];
      float4 o;
      o.x = w[0]*L0   + w[1]*F0.x + w[2]*F0.y
          + w[3]*L1   + w[4]*F1.x + w[5]*F1.y
          + w[6]*L2   + w[7]*F2.x + w[8]*F2.y;
      o.y = w[0]*F0.x + w[1]*F0.y + w[2]*F0.z
          + w[3]*F1.x + w[4]*F1.y + w[5]*F1.z
          + w[6]*F2.x + w[7]*F2.y + w[8]*F2.z;
      o.z = w[0]*F0.y + w[1]*F0.z + w[2]*F0.w
          + w[3]*F1.y + w[4]*F1.z + w[5]*F1.w
          + w[6]*F2.y + w[7]*F2.z + w[8]*F2.w;
      o.w = w[0]*F0.z + w[1]*F0.w + w[2]*R0
          + w[3]*F1.z + w[4]*F1.w + w[5]*R1
          + w[6]*F2.z + w[7]*F2.w + w[8]*R2;
      *(float4*)op = o;
      op += WW;
      L0 = L1; F0 = F1; R0 = R1;
      L1 = L2; F1 = F2; R1 = R2;
    }
  }
}

extern "C" void kernel_launch(void* const* d_in, const int* in_sizes, int n_in,
                              void* d_out, int out_size)
{
  const float* x    = (const float*)d_in[0];
  const float* Wv   = (const float*)d_in[1];
  const float* bv   = (const float*)d_in[2];
  const float* Wm   = (const float*)d_in[3];
  const float* bm   = (const float*)d_in[4];
  const float* gma  = (const float*)d_in[5];
  const float* bta  = (const float*)d_in[6];
  const float* mu   = (const float*)d_in[7];
  const float* var  = (const float*)d_in[8];
  const float* Wfc  = (const float*)d_in[9];
  const float* bfc  = (const float*)d_in[10];
  float* out = (float*)d_out;

  cudaFuncSetAttribute(attn_ctx_mma,
                       cudaFuncAttributeMaxDynamicSharedMemorySize, SMEMB);

  zero_ctx_kernel<<<256, 256>>>();
  attn_ctx_mma<<<dim3(BLKX, BATCH), 512, SMEMB>>>(
      x, Wv, bv, Wm, bm, gma, bta, mu, var);
  dynw_kernel<<<1024, 128>>>(Wfc, bfc);
  dwconv_kernel<<<dim3(BATCH * CH, HH / TROWS), 128>>>(x, out);
}